// round 17
// baseline (speedup 1.0000x reference)
#include <cuda_runtime.h>
#include <cstdint>

// LambdaLoss: B=4096 lists, L=128 items.
// loss = mean over valid lists of
//        [ sum_{i,j: rel_i>rel_j} (rel_i-rel_j)*softplus(-(p_i-p_j)) / cnt ]
//
// R17 — telescoped prefix products, TWO winners per thread.
// softplus(-(p_w-p_l)) = ln(1 + e_l*rec_w); counting-sort by rel.
// Winner w (class cw): contrib = sum_{m=1..cw} log2 PROD_{i<cumB[m]} (1+rec_w*e_i).
// Thread t64 owns sorted winners A=t64 and B=t64+64 (ctA <= ctB). Both walk
// the SAME loser prefix -> one zero-padded float4 load feeds both chains
// (2x load amortization, balanced warps, 2-chain ILP). When the whole warp's
// A chains are done (__all(ctA<m)), late segments run a B-only walk.
// Segments zero-padded to 8-aligned boundaries (pad factor == exactly 1):
// no scalar heads/tails. f32x2 factor generation; exponent harvesting keeps
// products in range; lg2 only at checkpoints. 0 MUFU per pair.

#define LL_B   4096
#define LL_L   128
#define LOG2E  1.4426950408889634f
#define LN2    0.6931471805599453f
#define PADCAP 168   // 128 + 5*7 worst-case padding

__device__ float g_sum   = 0.0f;
__device__ int   g_valid = 0;
__device__ int   g_done  = 0;

__device__ __forceinline__ float fast_ex2(float x) {
    float r; asm("ex2.approx.f32 %0, %1;" : "=f"(r) : "f"(x)); return r;
}
__device__ __forceinline__ float fast_lg2(float x) {
    float r; asm("lg2.approx.f32 %0, %1;" : "=f"(r) : "f"(x)); return r;
}

typedef unsigned long long ull;
__device__ __forceinline__ ull pack2(float lo, float hi) {
    ull d; asm("mov.b64 %0, {%1, %2};" : "=l"(d) : "f"(lo), "f"(hi)); return d;
}
__device__ __forceinline__ void unpack2(ull d, float& lo, float& hi) {
    asm("mov.b64 {%0, %1}, %2;" : "=f"(lo), "=f"(hi) : "l"(d));
}
__device__ __forceinline__ ull fma2(ull a, ull b, ull c) {
    ull d; asm("fma.rn.f32x2 %0, %1, %2, %3;" : "=l"(d) : "l"(a), "l"(b), "l"(c)); return d;
}
__device__ __forceinline__ ull mul2(ull a, ull b) {
    ull d; asm("mul.rn.f32x2 %0, %1, %2;" : "=l"(d) : "l"(a), "l"(b)); return d;
}

// extract exponent of P into EX, renormalize mantissa to [1,2)
#define HARVEST(P, EX)                                                    \
    {                                                                     \
        const unsigned _u = __float_as_uint(P);                           \
        EX += (int)(_u >> 23) - 127;                                      \
        (P) = __uint_as_float((_u & 0x007fffffu) | 0x3f800000u);          \
    }

__global__ __launch_bounds__(128) void ll_main_kernel(
    const float* __restrict__ pred,
    const float* __restrict__ rel,
    float* __restrict__ out)
{
    // two lists per block, 64 threads (2 warps) each
    __shared__ __align__(16) float SeP[2][PADCAP]; // padded e by class segment
    __shared__ float Srec[2][LL_L];                // rec by compact sorted idx
    __shared__ int   hist[2][8];
    __shared__ int   rankc[2][8];
    __shared__ int   cumB[2][6];
    __shared__ int   PB[2][6];
    __shared__ float wsum[4];

    const int t    = threadIdx.x;
    const int half = t >> 6;
    const int t64  = t & 63;
    const int list = blockIdx.x * 2 + half;

    const float* P = pred + list * LL_L;
    const float* R = rel  + list * LL_L;

    const float pa = P[t64],      ra = R[t64];
    const float pb = P[t64 + 64], rb = R[t64 + 64];
    const int   ca = (int)ra, cb = (int)rb;     // rel in {0..4}
    const float qa = pa * LOG2E, qb = pb * LOG2E;
    const float ea  = fast_ex2(qa), rca = fast_ex2(-qa);
    const float eb  = fast_ex2(qb), rcb = fast_ex2(-qb);

    if (t64 < 8) { hist[half][t64] = 0; rankc[half][t64] = 0; }
    for (int i = t64; i < PADCAP; i += 64) SeP[half][i] = 0.0f;
    __syncthreads();
    atomicAdd(&hist[half][ca], 1);
    atomicAdd(&hist[half][cb], 1);
    __syncthreads();
    if (t64 == 0) {
        int a = 0, pbv = 0;
#pragma unroll
        for (int cc = 0; cc < 5; cc++) {
            cumB[half][cc] = a;  PB[half][cc] = pbv;
            a   += hist[half][cc];
            pbv += (hist[half][cc] + 7) & ~7;
        }
        cumB[half][5] = a;  PB[half][5] = pbv;
    }
    __syncthreads();
    {
        const int rka = atomicAdd(&rankc[half][ca], 1);
        const int rkb = atomicAdd(&rankc[half][cb], 1);
        SeP [half][PB[half][ca]   + rka] = ea;
        SeP [half][PB[half][cb]   + rkb] = eb;
        Srec[half][cumB[half][ca] + rka] = rca;
        Srec[half][cumB[half][cb] + rkb] = rcb;
    }
    __syncthreads();

    // thread owns sorted winners A = t64, B = t64+64  (ctA <= ctB)
    const float recA = Srec[half][t64];
    const float recB = Srec[half][t64 + 64];
    const int b1 = cumB[half][1], b2 = cumB[half][2];
    const int b3 = cumB[half][3], b4 = cumB[half][4];
    const int ctA = (t64 >= b1) + (t64 >= b2) + (t64 >= b3) + (t64 >= b4);
    const int tb  = t64 + 64;
    const int ctB = (tb >= b1) + (tb >= b2) + (tb >= b3) + (tb >= b4);

    const float* Se = SeP[half];
    const ull rA2 = pack2(recA, recA);
    const ull rB2 = pack2(recB, recB);
    const ull one2 = pack2(1.0f, 1.0f);

    float accA = 0.0f, accB = 0.0f;
    float pA = 1.0f, pB = 1.0f;
    int   exA = 0,   exB = 0;
    int   j = 0;

#pragma unroll
    for (int m = 1; m <= 4; m++) {
        if (__all_sync(0xffffffffu, ctB < m)) break;
        const int j1 = PB[half][m];            // 8-aligned, list-uniform

        if (__any_sync(0xffffffffu, ctA >= m)) {
            while (j < j1) {                   // dual walk: A and B chains
                const float4 va = *reinterpret_cast<const float4*>(&Se[j]);
                const float4 vb = *reinterpret_cast<const float4*>(&Se[j + 4]);
                const ull e01 = pack2(va.x, va.y);
                const ull e23 = pack2(va.z, va.w);
                const ull e45 = pack2(vb.x, vb.y);
                const ull e67 = pack2(vb.z, vb.w);
                // A chain
                {
                    const ull f0 = fma2(rA2, e01, one2);
                    const ull f1 = fma2(rA2, e23, one2);
                    const ull f2 = fma2(rA2, e45, one2);
                    const ull f3 = fma2(rA2, e67, one2);
                    const ull m01 = mul2(f0, f1);
                    const ull m23 = mul2(f2, f3);
                    float g0, g1, h0, h1;
                    unpack2(m01, g0, g1);
                    unpack2(m23, h0, h1);
                    pA *= g0 * g1;  HARVEST(pA, exA)   // 4 factors
                    pA *= h0 * h1;  HARVEST(pA, exA)
                }
                // B chain
                {
                    const ull f0 = fma2(rB2, e01, one2);
                    const ull f1 = fma2(rB2, e23, one2);
                    const ull f2 = fma2(rB2, e45, one2);
                    const ull f3 = fma2(rB2, e67, one2);
                    const ull m01 = mul2(f0, f1);
                    const ull m23 = mul2(f2, f3);
                    float g0, g1, h0, h1;
                    unpack2(m01, g0, g1);
                    unpack2(m23, h0, h1);
                    pB *= g0 * g1;  HARVEST(pB, exB)
                    pB *= h0 * h1;  HARVEST(pB, exB)
                }
                j += 8;
            }
        } else {
            while (j < j1) {                   // B-only walk (A chains done)
                const float4 va = *reinterpret_cast<const float4*>(&Se[j]);
                const float4 vb = *reinterpret_cast<const float4*>(&Se[j + 4]);
                const ull f0 = fma2(rB2, pack2(va.x, va.y), one2);
                const ull f1 = fma2(rB2, pack2(va.z, va.w), one2);
                const ull f2 = fma2(rB2, pack2(vb.x, vb.y), one2);
                const ull f3 = fma2(rB2, pack2(vb.z, vb.w), one2);
                const ull m01 = mul2(f0, f1);
                const ull m23 = mul2(f2, f3);
                float g0, g1, h0, h1;
                unpack2(m01, g0, g1);
                unpack2(m23, h0, h1);
                pB *= g0 * g1;  HARVEST(pB, exB)
                pB *= h0 * h1;  HARVEST(pB, exB)
                j += 8;
            }
        }
        // checkpoints (pA, pB in [1,2) after harvest)
        if (ctA >= m) accA += (float)exA + fast_lg2(pA);
        if (ctB >= m) accB += (float)exB + fast_lg2(pB);
    }

    float acc = accA + accB;

    // warp reduction, then combine the list's two warps
#pragma unroll
    for (int off = 16; off; off >>= 1)
        acc += __shfl_xor_sync(0xffffffffu, acc, off);
    if ((t & 31) == 0) wsum[t >> 5] = acc;
    __syncthreads();

    if (t64 == 0) {
        const float s = (wsum[half * 2] + wsum[half * 2 + 1]) * LN2;
        const int n0 = hist[half][0], n1 = hist[half][1], n2 = hist[half][2];
        const int n3 = hist[half][3], n4 = hist[half][4];
        const int cnt = n1 * n0
                      + n2 * (n0 + n1)
                      + n3 * (n0 + n1 + n2)
                      + n4 * (n0 + n1 + n2 + n3);
        if (cnt > 0) {
            atomicAdd(&g_sum, s / (float)cnt);
            atomicAdd(&g_valid, 1);
        }
        __threadfence();
        const int prev = atomicAdd(&g_done, 1);
        if (prev == LL_B - 1) {
            const float gs = g_sum;
            const int   gv = g_valid;
            out[0] = (gv > 0) ? (gs / (float)gv) : 0.0f;
            g_sum   = 0.0f;
            g_valid = 0;
            g_done  = 0;
        }
    }
}

extern "C" void kernel_launch(void* const* d_in, const int* in_sizes, int n_in,
                              void* d_out, int out_size)
{
    const float* pred = (const float*)d_in[0];
    const float* rel  = (const float*)d_in[1];
    float* out = (float*)d_out;

    ll_main_kernel<<<LL_B / 2, 128>>>(pred, rel, out);
}